// round 15
// baseline (speedup 1.0000x reference)
#include <cuda_runtime.h>
#include <math.h>
#include <stdint.h>

// ---------------------------------------------------------------------------
// GAT_23888608101379: 3-layer GAT + mean pool + linear head.
//  R12: - double-buffered tf32 GEMM (reg-staged, 1 barrier/tile, 2 blocks/SM)
//       - multi-block shuffle scan (was single-block bottleneck)
//       - warp-per-dst aggregation with float4 gathers
//       - softmax normalization folded into aggregation (g_inv)
//       - convert+hist merged
// ---------------------------------------------------------------------------

constexpr int CN = 50000;            // nodes
constexpr int CE = 800000;           // edges
constexpr int CT = CE + CN;          // edges + self loops

__device__ float g_bufA[(size_t)CN * 256];
__device__ float g_bufB[(size_t)CN * 256];
__device__ float g_h2  [(size_t)CN * 64];
__device__ float g_out2[(size_t)CN * 64];
__device__ float g_as  [CN * 4];
__device__ float g_ad  [CN * 4];
__device__ float g_inv [CN * 4];
__device__ float g_w   [(size_t)CT * 4];
__device__ int   g_src [CE];
__device__ int   g_dst [CE];
__device__ int   g_rowptr[CN + 1];
__device__ int   g_counts[CN];
__device__ int   g_cursor[CN];
__device__ int   g_adj   [CT];
__device__ int   g_bsum[64];
__device__ float g_gsum[64];
__device__ int   g_is64;

// ----------------------- edge dtype detect ---------------------------------

__global__ void k_detect(const int* __restrict__ w) {
    __shared__ int any;
    if (threadIdx.x == 0) any = 0;
    __syncthreads();
    for (int i = threadIdx.x; i < 4096; i += blockDim.x)
        if (w[2 * i + 1] != 0) any = 1;
    __syncthreads();
    if (threadIdx.x == 0) g_is64 = (any == 0) ? 1 : 0;
}

__global__ void k_init(int n) {
    int i = blockIdx.x * blockDim.x + threadIdx.x;
    if (i < n)  g_counts[i] = 1;      // self loop
    if (i < 64) g_gsum[i] = 0.f;
}

// convert (int32/int64) + histogram in one pass
__global__ void k_prep(const void* __restrict__ ei, int e, int n) {
    int i = blockIdx.x * blockDim.x + threadIdx.x;
    if (i >= e) return;
    int s, d;
    if (g_is64) {
        const long long* p = (const long long*)ei;
        s = (int)p[i];
        d = (int)p[(size_t)e + i];
    } else {
        const int* p = (const int*)ei;
        s = p[i];
        d = p[(size_t)e + i];
    }
    g_src[i] = s;
    g_dst[i] = d;
    if (d >= 0 && d < n) atomicAdd(&g_counts[d], 1);
}

// ------------------------- multi-block scan ---------------------------------

__global__ void k_scan1(int n) {
    int b = blockIdx.x;
    int i = b * 1024 + threadIdx.x;
    int v = (i < n) ? g_counts[i] : 0;
    int lane = threadIdx.x & 31, wid = threadIdx.x >> 5;
    int s = v;
    #pragma unroll
    for (int off = 1; off < 32; off <<= 1) {
        int t = __shfl_up_sync(0xffffffffu, s, off);
        if (lane >= off) s += t;
    }
    __shared__ int wsum[32];
    if (lane == 31) wsum[wid] = s;
    __syncthreads();
    if (wid == 0) {
        int ws = wsum[lane];
        #pragma unroll
        for (int off = 1; off < 32; off <<= 1) {
            int t = __shfl_up_sync(0xffffffffu, ws, off);
            if (lane >= off) ws += t;
        }
        wsum[lane] = ws;
    }
    __syncthreads();
    int base = (wid > 0) ? wsum[wid - 1] : 0;
    int excl = base + s - v;
    if (i < n) g_rowptr[i] = excl;
    if (threadIdx.x == 1023) g_bsum[b] = excl + v;
}

__global__ void k_scan2(int nb, int n) {
    int t = threadIdx.x;                     // 64 threads, nb <= 64
    int v = (t < nb) ? g_bsum[t] : 0;
    int lane = t & 31, w = t >> 5;
    int s = v;
    #pragma unroll
    for (int off = 1; off < 32; off <<= 1) {
        int tt = __shfl_up_sync(0xffffffffu, s, off);
        if (lane >= off) s += tt;
    }
    __shared__ int ws0;
    if (w == 0 && lane == 31) ws0 = s;
    __syncthreads();
    int incl = s + ((w == 1) ? ws0 : 0);
    int excl = incl - v;
    if (t < nb) g_bsum[t] = excl;
    if (t == nb - 1) g_rowptr[n] = incl;
}

__global__ void k_scan3(int n) {
    int i = blockIdx.x * blockDim.x + threadIdx.x;
    if (i < n) {
        int rp = g_rowptr[i] + g_bsum[i >> 10];
        g_rowptr[i] = rp;
        g_cursor[i] = rp;
    }
}

__global__ void k_scatter(int e, int n) {
    int i = blockIdx.x * blockDim.x + threadIdx.x;
    if (i < e) {
        int s = g_src[i];
        int d = g_dst[i];
        if (d >= 0 && d < n && s >= 0 && s < n) {
            int pos = atomicAdd(&g_cursor[d], 1);
            g_adj[pos] = s;
        }
    } else if (i < e + n) {
        int nd = i - e;                       // self loop
        int pos = atomicAdd(&g_cursor[nd], 1);
        g_adj[pos] = nd;
    }
}

// ------------------ double-buffered tf32 tensor-core GEMM -------------------
// C[M,N] = A[M,K] @ B[K,N]; BM=128, BN=64, BK=32; 256 threads (8 warps,
// WM=WN=32). Register-staged global loads; one barrier per K-tile.

__device__ __forceinline__ uint32_t f2tf32(float f) {
    uint32_t u;
    asm("cvt.rna.tf32.f32 %0, %1;" : "=r"(u) : "f"(f));
    return u;
}

__device__ __forceinline__ void mma_tf32(float* c,
                                         const uint32_t* a, const uint32_t* b) {
    asm volatile(
        "mma.sync.aligned.m16n8k8.row.col.f32.tf32.tf32.f32 "
        "{%0,%1,%2,%3}, {%4,%5,%6,%7}, {%8,%9}, {%0,%1,%2,%3};\n"
        : "+f"(c[0]), "+f"(c[1]), "+f"(c[2]), "+f"(c[3])
        : "r"(a[0]), "r"(a[1]), "r"(a[2]), "r"(a[3]), "r"(b[0]), "r"(b[1]));
}

template <int BN>
__global__ __launch_bounds__(256, 2) void k_gemm_db(const float* __restrict__ A,
                                                    const float* __restrict__ B,
                                                    float* __restrict__ C,
                                                    int M, int N, int K) {
    constexpr int WM = 32, WN = 32;
    constexpr int WARPS_M = 128 / WM;            // 4
    constexpr int MT = WM / 16;                  // 2
    constexpr int NT = WN / 8;                   // 4
    constexpr int BITER = (32 * BN) / 1024;      // float4s of B per thread

    __shared__ uint32_t As[2][128][32];
    __shared__ uint32_t Bs[2][BN][32];

    const int tid  = threadIdx.x;
    const int wid  = tid >> 5;
    const int lane = tid & 31;
    const int g    = lane >> 2;
    const int tg   = lane & 3;
    const int sw   = g << 2;

    const int wm = wid % WARPS_M;
    const int wn = wid / WARPS_M;
    const int rowBase = blockIdx.x * 128;
    const int colBase = blockIdx.y * BN;

    float4 ra[4];
    float4 rb[BITER];

    auto gload = [&](int k0) {
        #pragma unroll
        for (int it = 0; it < 4; ++it) {
            int idx = tid + it * 256;
            int r = idx >> 3, c4 = (idx & 7) << 2;
            int gr = rowBase + r;
            ra[it] = (gr < M)
                ? *reinterpret_cast<const float4*>(A + (size_t)gr * K + k0 + c4)
                : make_float4(0.f, 0.f, 0.f, 0.f);
        }
        #pragma unroll
        for (int it = 0; it < BITER; ++it) {
            int idx = tid + it * 256;
            int n4 = (idx & (BN / 4 - 1)) * 4;
            int k  = idx / (BN / 4);
            rb[it] = *reinterpret_cast<const float4*>(
                B + (size_t)(k0 + k) * N + colBase + n4);
        }
    };
    auto sstore = [&](int buf) {
        #pragma unroll
        for (int it = 0; it < 4; ++it) {
            int idx = tid + it * 256;
            int r = idx >> 3, c4 = (idx & 7) << 2;
            int cs = c4 ^ ((r & 7) << 2);
            *reinterpret_cast<uint4*>(&As[buf][r][cs]) =
                make_uint4(f2tf32(ra[it].x), f2tf32(ra[it].y),
                           f2tf32(ra[it].z), f2tf32(ra[it].w));
        }
        #pragma unroll
        for (int it = 0; it < BITER; ++it) {
            int idx = tid + it * 256;
            int n4 = (idx & (BN / 4 - 1)) * 4;
            int k  = idx / (BN / 4);
            Bs[buf][n4 + 0][k ^ (((n4 + 0) & 7) << 2)] = f2tf32(rb[it].x);
            Bs[buf][n4 + 1][k ^ (((n4 + 1) & 7) << 2)] = f2tf32(rb[it].y);
            Bs[buf][n4 + 2][k ^ (((n4 + 2) & 7) << 2)] = f2tf32(rb[it].z);
            Bs[buf][n4 + 3][k ^ (((n4 + 3) & 7) << 2)] = f2tf32(rb[it].w);
        }
    };

    float acc[MT][NT][4];
    #pragma unroll
    for (int mi = 0; mi < MT; mi++)
        #pragma unroll
        for (int ni = 0; ni < NT; ni++)
            #pragma unroll
            for (int q = 0; q < 4; q++) acc[mi][ni][q] = 0.f;

    gload(0);
    sstore(0);
    __syncthreads();

    const int KT = K / 32;
    for (int kt = 0; kt < KT; ++kt) {
        if (kt + 1 < KT) gload((kt + 1) * 32);
        int buf = kt & 1;
        #pragma unroll
        for (int kk = 0; kk < 32; kk += 8) {
            uint32_t af[MT][4], bf[NT][2];
            int c0 = (kk + tg) ^ sw;
            int c1 = (kk + tg + 4) ^ sw;
            #pragma unroll
            for (int mi = 0; mi < MT; mi++) {
                int r0 = wm * WM + mi * 16 + g;
                af[mi][0] = As[buf][r0][c0];
                af[mi][1] = As[buf][r0 + 8][c0];
                af[mi][2] = As[buf][r0][c1];
                af[mi][3] = As[buf][r0 + 8][c1];
            }
            #pragma unroll
            for (int ni = 0; ni < NT; ni++) {
                int nn = wn * WN + ni * 8 + g;
                bf[ni][0] = Bs[buf][nn][c0];
                bf[ni][1] = Bs[buf][nn][c1];
            }
            #pragma unroll
            for (int mi = 0; mi < MT; mi++)
                #pragma unroll
                for (int ni = 0; ni < NT; ni++)
                    mma_tf32(acc[mi][ni], af[mi], bf[ni]);
        }
        if (kt + 1 < KT) {
            sstore((kt + 1) & 1);
            __syncthreads();
        }
    }

    #pragma unroll
    for (int mi = 0; mi < MT; mi++) {
        int r = rowBase + wm * WM + mi * 16 + g;
        #pragma unroll
        for (int ni = 0; ni < NT; ni++) {
            int c = colBase + wn * WN + ni * 8 + tg * 2;
            if (r < M)
                *reinterpret_cast<float2*>(C + (size_t)r * N + c) =
                    make_float2(acc[mi][ni][0], acc[mi][ni][1]);
            if (r + 8 < M)
                *reinterpret_cast<float2*>(C + (size_t)(r + 8) * N + c) =
                    make_float2(acc[mi][ni][2], acc[mi][ni][3]);
        }
    }
}

// ----------------------- attention scalar dots ------------------------------

template <int H>
__global__ void k_alpha(const float* __restrict__ h, const float* __restrict__ av_s,
                        const float* __restrict__ av_d, int n) {
    int gw = (blockIdx.x * blockDim.x + threadIdx.x) >> 5;
    int lane = threadIdx.x & 31;
    if (gw >= n) return;
    const int HC = H * 64;
    float ps[H], pd[H];
    #pragma unroll
    for (int hh = 0; hh < H; ++hh) { ps[hh] = 0.f; pd[hh] = 0.f; }
    #pragma unroll
    for (int i = 0; i < HC / 32; ++i) {
        int idx = lane + i * 32;
        float hv = h[(size_t)gw * HC + idx];
        ps[i >> 1] += hv * av_s[idx];
        pd[i >> 1] += hv * av_d[idx];
    }
    #pragma unroll
    for (int hh = 0; hh < H; ++hh) {
        #pragma unroll
        for (int off = 16; off > 0; off >>= 1) {
            ps[hh] += __shfl_xor_sync(0xffffffffu, ps[hh], off);
            pd[hh] += __shfl_xor_sync(0xffffffffu, pd[hh], off);
        }
    }
    if (lane == 0) {
        #pragma unroll
        for (int hh = 0; hh < H; ++hh) {
            g_as[gw * H + hh] = ps[hh];
            g_ad[gw * H + hh] = pd[hh];
        }
    }
}

// ------------- per-dst softmax (2 passes; normalization deferred) -----------

template <int H>
__global__ void k_att(int n) {
    int gw = (blockIdx.x * blockDim.x + threadIdx.x) >> 5;
    int lane = threadIdx.x & 31;
    if (gw >= n) return;
    int r0 = g_rowptr[gw], r1 = g_rowptr[gw + 1];
    float ad[H], mx[H];
    #pragma unroll
    for (int hh = 0; hh < H; ++hh) { ad[hh] = g_ad[gw * H + hh]; mx[hh] = -1e30f; }
    for (int p = r0 + lane; p < r1; p += 32) {
        int s = g_adj[p];
        #pragma unroll
        for (int hh = 0; hh < H; ++hh) {
            float e = g_as[s * H + hh] + ad[hh];
            e = (e > 0.f) ? e : 0.2f * e;        // leaky_relu 0.2
            g_w[(size_t)p * H + hh] = e;
            mx[hh] = fmaxf(mx[hh], e);
        }
    }
    #pragma unroll
    for (int hh = 0; hh < H; ++hh)
        #pragma unroll
        for (int off = 16; off > 0; off >>= 1)
            mx[hh] = fmaxf(mx[hh], __shfl_xor_sync(0xffffffffu, mx[hh], off));
    float sm[H];
    #pragma unroll
    for (int hh = 0; hh < H; ++hh) sm[hh] = 0.f;
    for (int p = r0 + lane; p < r1; p += 32) {
        #pragma unroll
        for (int hh = 0; hh < H; ++hh) {
            float ex = expf(g_w[(size_t)p * H + hh] - mx[hh]);
            g_w[(size_t)p * H + hh] = ex;       // unnormalized; g_inv fixes it
            sm[hh] += ex;
        }
    }
    #pragma unroll
    for (int hh = 0; hh < H; ++hh)
        #pragma unroll
        for (int off = 16; off > 0; off >>= 1)
            sm[hh] += __shfl_xor_sync(0xffffffffu, sm[hh], off);
    if (lane == 0) {
        #pragma unroll
        for (int hh = 0; hh < H; ++hh)
            g_inv[gw * H + hh] = 1.f / (sm[hh] + 1e-16f);
    }
}

// --------------------------- aggregation (warp/dst) -------------------------
// H=4: lane owns 8 contiguous cols (head = lane/8). float4 gathers.

template <bool RELU>
__global__ void k_agg4(const float* __restrict__ hin, const float* __restrict__ bias,
                       float* __restrict__ out, int n) {
    int dst = (blockIdx.x * blockDim.x + threadIdx.x) >> 5;
    int lane = threadIdx.x & 31;
    if (dst >= n) return;
    int head = lane >> 3;
    int cb = lane << 3;
    float acc[8];
    #pragma unroll
    for (int q = 0; q < 8; q++) acc[q] = 0.f;
    int p = g_rowptr[dst], pe = g_rowptr[dst + 1];
    for (; p + 1 < pe; p += 2) {
        int sA = g_adj[p], sB = g_adj[p + 1];
        float wA = g_w[(size_t)p * 4 + head];
        float wB = g_w[(size_t)(p + 1) * 4 + head];
        const float* hA = hin + (size_t)sA * 256 + cb;
        const float* hB = hin + (size_t)sB * 256 + cb;
        float4 a0 = *reinterpret_cast<const float4*>(hA);
        float4 a1 = *reinterpret_cast<const float4*>(hA + 4);
        float4 b0 = *reinterpret_cast<const float4*>(hB);
        float4 b1 = *reinterpret_cast<const float4*>(hB + 4);
        acc[0] = fmaf(wA, a0.x, acc[0]); acc[1] = fmaf(wA, a0.y, acc[1]);
        acc[2] = fmaf(wA, a0.z, acc[2]); acc[3] = fmaf(wA, a0.w, acc[3]);
        acc[4] = fmaf(wA, a1.x, acc[4]); acc[5] = fmaf(wA, a1.y, acc[5]);
        acc[6] = fmaf(wA, a1.z, acc[6]); acc[7] = fmaf(wA, a1.w, acc[7]);
        acc[0] = fmaf(wB, b0.x, acc[0]); acc[1] = fmaf(wB, b0.y, acc[1]);
        acc[2] = fmaf(wB, b0.z, acc[2]); acc[3] = fmaf(wB, b0.w, acc[3]);
        acc[4] = fmaf(wB, b1.x, acc[4]); acc[5] = fmaf(wB, b1.y, acc[5]);
        acc[6] = fmaf(wB, b1.z, acc[6]); acc[7] = fmaf(wB, b1.w, acc[7]);
    }
    if (p < pe) {
        int s = g_adj[p];
        float w = g_w[(size_t)p * 4 + head];
        const float* hA = hin + (size_t)s * 256 + cb;
        float4 a0 = *reinterpret_cast<const float4*>(hA);
        float4 a1 = *reinterpret_cast<const float4*>(hA + 4);
        acc[0] = fmaf(w, a0.x, acc[0]); acc[1] = fmaf(w, a0.y, acc[1]);
        acc[2] = fmaf(w, a0.z, acc[2]); acc[3] = fmaf(w, a0.w, acc[3]);
        acc[4] = fmaf(w, a1.x, acc[4]); acc[5] = fmaf(w, a1.y, acc[5]);
        acc[6] = fmaf(w, a1.z, acc[6]); acc[7] = fmaf(w, a1.w, acc[7]);
    }
    float inv = g_inv[dst * 4 + head];
    float4 bv0 = *reinterpret_cast<const float4*>(bias + cb);
    float4 bv1 = *reinterpret_cast<const float4*>(bias + cb + 4);
    float4 o0, o1;
    o0.x = fmaf(acc[0], inv, bv0.x); o0.y = fmaf(acc[1], inv, bv0.y);
    o0.z = fmaf(acc[2], inv, bv0.z); o0.w = fmaf(acc[3], inv, bv0.w);
    o1.x = fmaf(acc[4], inv, bv1.x); o1.y = fmaf(acc[5], inv, bv1.y);
    o1.z = fmaf(acc[6], inv, bv1.z); o1.w = fmaf(acc[7], inv, bv1.w);
    if (RELU) {
        o0.x = fmaxf(o0.x, 0.f); o0.y = fmaxf(o0.y, 0.f);
        o0.z = fmaxf(o0.z, 0.f); o0.w = fmaxf(o0.w, 0.f);
        o1.x = fmaxf(o1.x, 0.f); o1.y = fmaxf(o1.y, 0.f);
        o1.z = fmaxf(o1.z, 0.f); o1.w = fmaxf(o1.w, 0.f);
    }
    float* op = out + (size_t)dst * 256 + cb;
    *reinterpret_cast<float4*>(op) = o0;
    *reinterpret_cast<float4*>(op + 4) = o1;
}

// H=1 (HC=64): lane owns 2 cols, float2 gathers.
template <bool RELU>
__global__ void k_agg1(const float* __restrict__ hin, const float* __restrict__ bias,
                       float* __restrict__ out, int n) {
    int dst = (blockIdx.x * blockDim.x + threadIdx.x) >> 5;
    int lane = threadIdx.x & 31;
    if (dst >= n) return;
    int cb = lane << 1;
    float a0 = 0.f, a1 = 0.f;
    int p = g_rowptr[dst], pe = g_rowptr[dst + 1];
    for (; p + 1 < pe; p += 2) {
        int sA = g_adj[p], sB = g_adj[p + 1];
        float wA = g_w[p], wB = g_w[p + 1];
        float2 hA = *reinterpret_cast<const float2*>(hin + (size_t)sA * 64 + cb);
        float2 hB = *reinterpret_cast<const float2*>(hin + (size_t)sB * 64 + cb);
        a0 = fmaf(wA, hA.x, a0); a1 = fmaf(wA, hA.y, a1);
        a0 = fmaf(wB, hB.x, a0); a1 = fmaf(wB, hB.y, a1);
    }
    if (p < pe) {
        int s = g_adj[p];
        float w = g_w[p];
        float2 hA = *reinterpret_cast<const float2*>(hin + (size_t)s * 64 + cb);
        a0 = fmaf(w, hA.x, a0); a1 = fmaf(w, hA.y, a1);
    }
    float inv = g_inv[dst];
    float2 bv = *reinterpret_cast<const float2*>(bias + cb);
    float2 o;
    o.x = fmaf(a0, inv, bv.x);
    o.y = fmaf(a1, inv, bv.y);
    if (RELU) { o.x = fmaxf(o.x, 0.f); o.y = fmaxf(o.y, 0.f); }
    *reinterpret_cast<float2*>(out + (size_t)dst * 64 + cb) = o;
}

// ------------------------- mean pool + head ---------------------------------

__global__ void k_reduce(const float* __restrict__ h2, int n) {
    __shared__ float sh[256];
    int c = threadIdx.x & 63;
    int rl = threadIdx.x >> 6;
    int rbase = blockIdx.x * 256;
    int rend = min(n, rbase + 256);
    float acc = 0.f;
    for (int r = rbase + rl; r < rend; r += 4)
        acc += h2[(size_t)r * 64 + c];
    sh[threadIdx.x] = acc;
    __syncthreads();
    if (threadIdx.x < 64) {
        float v = sh[threadIdx.x] + sh[threadIdx.x + 64] +
                  sh[threadIdx.x + 128] + sh[threadIdx.x + 192];
        atomicAdd(&g_gsum[threadIdx.x], v);
    }
}

__global__ void k_head(const float* __restrict__ hw, const float* __restrict__ hb,
                       float* __restrict__ out, float invN) {
    int o = threadIdx.x;   // 64 threads
    float acc = hb[o];
    #pragma unroll 8
    for (int c = 0; c < 64; ++c)
        acc = fmaf(g_gsum[c] * invN, hw[c * 64 + o], acc);
    out[o] = acc;
}

// ------------------------------ launch --------------------------------------

extern "C" void kernel_launch(void* const* d_in, const int* in_sizes, int n_in,
                              void* d_out, int out_size) {
    const float* x   = (const float*)d_in[0];
    const void*  ei  = d_in[1];
    const float* W0  = (const float*)d_in[2];
    const float* a0s = (const float*)d_in[3];
    const float* a0d = (const float*)d_in[4];
    const float* b0  = (const float*)d_in[5];
    const float* W1  = (const float*)d_in[6];
    const float* a1s = (const float*)d_in[7];
    const float* a1d = (const float*)d_in[8];
    const float* b1  = (const float*)d_in[9];
    const float* W2  = (const float*)d_in[10];
    const float* a2s = (const float*)d_in[11];
    const float* a2d = (const float*)d_in[12];
    const float* b2  = (const float*)d_in[13];
    const float* hw  = (const float*)d_in[14];
    const float* hb  = (const float*)d_in[15];
    float* out = (float*)d_out;

    int n = in_sizes[0] / 128;   // 50000
    int e = in_sizes[1] / 2;     // 800000

    float *bufA, *bufB, *h2p, *out2p;
    cudaGetSymbolAddress((void**)&bufA,  g_bufA);
    cudaGetSymbolAddress((void**)&bufB,  g_bufB);
    cudaGetSymbolAddress((void**)&h2p,   g_h2);
    cudaGetSymbolAddress((void**)&out2p, g_out2);

    int wblocks = (n + 7) / 8;                 // warp-per-node kernels
    int nb = (n + 1023) / 1024;

    // CSR build (by dst, with implicit self loops)
    k_init   <<<(n + 255) / 256, 256>>>(n);
    k_detect <<<1, 256>>>((const int*)ei);
    k_prep   <<<(e + 255) / 256, 256>>>(ei, e, n);
    k_scan1  <<<nb, 1024>>>(n);
    k_scan2  <<<1, 64>>>(nb, n);
    k_scan3  <<<nb, 1024>>>(n);
    k_scatter<<<(e + n + 255) / 256, 256>>>(e, n);

    dim3 g01((n + 127) / 128, 4);              // N=256, BN=64
    dim3 g2 ((n + 127) / 128, 1);              // N=64

    // ---- layer 0 ----
    k_gemm_db<64><<<g01, 256>>>(x, W0, bufA, n, 256, 128);
    k_alpha<4><<<wblocks, 256>>>(bufA, a0s, a0d, n);
    k_att<4><<<wblocks, 256>>>(n);
    k_agg4<true><<<(n + 7) / 8, 256>>>(bufA, b0, bufB, n);

    // ---- layer 1 ----
    k_gemm_db<64><<<g01, 256>>>(bufB, W1, bufA, n, 256, 256);
    k_alpha<4><<<wblocks, 256>>>(bufA, a1s, a1d, n);
    k_att<4><<<wblocks, 256>>>(n);
    k_agg4<true><<<(n + 7) / 8, 256>>>(bufA, b1, bufB, n);

    // ---- layer 2 ----
    k_gemm_db<64><<<g2, 256>>>(bufB, W2, h2p, n, 64, 256);
    k_alpha<1><<<wblocks, 256>>>(h2p, a2s, a2d, n);
    k_att<1><<<wblocks, 256>>>(n);
    k_agg1<false><<<(n + 7) / 8, 256>>>(h2p, b2, out2p, n);

    // ---- mean over nodes + linear head ----
    k_reduce<<<(n + 255) / 256, 256>>>(out2p, n);
    k_head<<<1, 64>>>(hw, hb, out, 1.0f / (float)n);
}

// round 16
// speedup vs baseline: 1.2497x; 1.2497x over previous
#include <cuda_runtime.h>
#include <cuda_fp16.h>
#include <math.h>
#include <stdint.h>

// ---------------------------------------------------------------------------
// GAT_23888608101379: 3-layer GAT + mean pool + linear head.
//  R15: - alpha dots fused into GEMM epilogue (BN=64 == head width)
//       - h stored fp16 (half2 epilogue); aggregation gathers 16B/lane/edge
//       - k_alpha kernels removed
// ---------------------------------------------------------------------------

constexpr int CN = 50000;            // nodes
constexpr int CE = 800000;           // edges
constexpr int CT = CE + CN;          // edges + self loops

__device__ __half g_hA [(size_t)CN * 256];   // h (layers 0/1), fp16
__device__ __half g_h2h[(size_t)CN * 64];    // h (layer 2), fp16
__device__ float  g_bufB[(size_t)CN * 256];  // agg output (GEMM input)
__device__ float  g_out2[(size_t)CN * 64];
__device__ float  g_as  [CN * 4];
__device__ float  g_ad  [CN * 4];
__device__ float  g_inv [CN * 4];
__device__ float  g_w   [(size_t)CT * 4];
__device__ int    g_src [CE];
__device__ int    g_dst [CE];
__device__ int    g_rowptr[CN + 1];
__device__ int    g_counts[CN];
__device__ int    g_cursor[CN];
__device__ int    g_adj   [CT];
__device__ int    g_bsum[64];
__device__ float  g_gsum[64];
__device__ int    g_is64;

// ----------------------- edge dtype detect ---------------------------------

__global__ void k_detect(const int* __restrict__ w) {
    __shared__ int any;
    if (threadIdx.x == 0) any = 0;
    __syncthreads();
    for (int i = threadIdx.x; i < 4096; i += blockDim.x)
        if (w[2 * i + 1] != 0) any = 1;
    __syncthreads();
    if (threadIdx.x == 0) g_is64 = (any == 0) ? 1 : 0;
}

__global__ void k_init(int n) {
    int i = blockIdx.x * blockDim.x + threadIdx.x;
    if (i < n)  g_counts[i] = 1;      // self loop
    if (i < 64) g_gsum[i] = 0.f;
}

// convert (int32/int64) + histogram in one pass
__global__ void k_prep(const void* __restrict__ ei, int e, int n) {
    int i = blockIdx.x * blockDim.x + threadIdx.x;
    if (i >= e) return;
    int s, d;
    if (g_is64) {
        const long long* p = (const long long*)ei;
        s = (int)p[i];
        d = (int)p[(size_t)e + i];
    } else {
        const int* p = (const int*)ei;
        s = p[i];
        d = p[(size_t)e + i];
    }
    g_src[i] = s;
    g_dst[i] = d;
    if (d >= 0 && d < n) atomicAdd(&g_counts[d], 1);
}

// ------------------------- multi-block scan ---------------------------------

__global__ void k_scan1(int n) {
    int b = blockIdx.x;
    int i = b * 1024 + threadIdx.x;
    int v = (i < n) ? g_counts[i] : 0;
    int lane = threadIdx.x & 31, wid = threadIdx.x >> 5;
    int s = v;
    #pragma unroll
    for (int off = 1; off < 32; off <<= 1) {
        int t = __shfl_up_sync(0xffffffffu, s, off);
        if (lane >= off) s += t;
    }
    __shared__ int wsum[32];
    if (lane == 31) wsum[wid] = s;
    __syncthreads();
    if (wid == 0) {
        int ws = wsum[lane];
        #pragma unroll
        for (int off = 1; off < 32; off <<= 1) {
            int t = __shfl_up_sync(0xffffffffu, ws, off);
            if (lane >= off) ws += t;
        }
        wsum[lane] = ws;
    }
    __syncthreads();
    int base = (wid > 0) ? wsum[wid - 1] : 0;
    int excl = base + s - v;
    if (i < n) g_rowptr[i] = excl;
    if (threadIdx.x == 1023) g_bsum[b] = excl + v;
}

__global__ void k_scan2(int nb, int n) {
    int t = threadIdx.x;                     // 64 threads, nb <= 64
    int v = (t < nb) ? g_bsum[t] : 0;
    int lane = t & 31, w = t >> 5;
    int s = v;
    #pragma unroll
    for (int off = 1; off < 32; off <<= 1) {
        int tt = __shfl_up_sync(0xffffffffu, s, off);
        if (lane >= off) s += tt;
    }
    __shared__ int ws0;
    if (w == 0 && lane == 31) ws0 = s;
    __syncthreads();
    int incl = s + ((w == 1) ? ws0 : 0);
    int excl = incl - v;
    if (t < nb) g_bsum[t] = excl;
    if (t == nb - 1) g_rowptr[n] = incl;
}

__global__ void k_scan3(int n) {
    int i = blockIdx.x * blockDim.x + threadIdx.x;
    if (i < n) {
        int rp = g_rowptr[i] + g_bsum[i >> 10];
        g_rowptr[i] = rp;
        g_cursor[i] = rp;
    }
}

__global__ void k_scatter(int e, int n) {
    int i = blockIdx.x * blockDim.x + threadIdx.x;
    if (i < e) {
        int s = g_src[i];
        int d = g_dst[i];
        if (d >= 0 && d < n && s >= 0 && s < n) {
            int pos = atomicAdd(&g_cursor[d], 1);
            g_adj[pos] = s;
        }
    } else if (i < e + n) {
        int nd = i - e;                       // self loop
        int pos = atomicAdd(&g_cursor[nd], 1);
        g_adj[pos] = nd;
    }
}

// -------- double-buffered tf32 GEMM + fused alpha epilogue, fp16 C ----------
// C[M,N] = A[M,K] @ B[K,N]; BM=128, BN=64, BK=32; 256 threads (8 warps,
// WM=WN=32, 4x2 warp grid). BN==64 == head width, so alpha_s/alpha_d for
// head = blockIdx.y are fully computable in-block from fp32 accumulators.

__device__ __forceinline__ uint32_t f2tf32(float f) {
    uint32_t u;
    asm("cvt.rna.tf32.f32 %0, %1;" : "=r"(u) : "f"(f));
    return u;
}

__device__ __forceinline__ void mma_tf32(float* c,
                                         const uint32_t* a, const uint32_t* b) {
    asm volatile(
        "mma.sync.aligned.m16n8k8.row.col.f32.tf32.tf32.f32 "
        "{%0,%1,%2,%3}, {%4,%5,%6,%7}, {%8,%9}, {%0,%1,%2,%3};\n"
        : "+f"(c[0]), "+f"(c[1]), "+f"(c[2]), "+f"(c[3])
        : "r"(a[0]), "r"(a[1]), "r"(a[2]), "r"(a[3]), "r"(b[0]), "r"(b[1]));
}

template <int H>
__global__ __launch_bounds__(256, 2) void k_gemm_f(const float* __restrict__ A,
                                                   const float* __restrict__ B,
                                                   __half* __restrict__ C,
                                                   const float* __restrict__ av_s,
                                                   const float* __restrict__ av_d,
                                                   int M, int N, int K) {
    constexpr int BN = 64, WM = 32, WN = 32;
    constexpr int WARPS_M = 4;
    constexpr int MT = 2, NT = 4;
    constexpr int BITER = 2;                     // (32*64)/1024 float4/thread

    __shared__ uint32_t As[2][128][32];
    __shared__ uint32_t Bs[2][BN][32];
    __shared__ float sred[128][2];

    const int tid  = threadIdx.x;
    const int wid  = tid >> 5;
    const int lane = tid & 31;
    const int g    = lane >> 2;
    const int tg   = lane & 3;
    const int sw   = g << 2;

    const int wm = wid % WARPS_M;
    const int wn = wid / WARPS_M;
    const int rowBase = blockIdx.x * 128;
    const int colBase = blockIdx.y * BN;
    const int head = blockIdx.y;                 // BN == head width

    float4 ra[4];
    float4 rb[BITER];

    auto gload = [&](int k0) {
        #pragma unroll
        for (int it = 0; it < 4; ++it) {
            int idx = tid + it * 256;
            int r = idx >> 3, c4 = (idx & 7) << 2;
            int gr = rowBase + r;
            ra[it] = (gr < M)
                ? *reinterpret_cast<const float4*>(A + (size_t)gr * K + k0 + c4)
                : make_float4(0.f, 0.f, 0.f, 0.f);
        }
        #pragma unroll
        for (int it = 0; it < BITER; ++it) {
            int idx = tid + it * 256;
            int n4 = (idx & (BN / 4 - 1)) * 4;
            int k  = idx / (BN / 4);
            rb[it] = *reinterpret_cast<const float4*>(
                B + (size_t)(k0 + k) * N + colBase + n4);
        }
    };
    auto sstore = [&](int buf) {
        #pragma unroll
        for (int it = 0; it < 4; ++it) {
            int idx = tid + it * 256;
            int r = idx >> 3, c4 = (idx & 7) << 2;
            int cs = c4 ^ ((r & 7) << 2);
            *reinterpret_cast<uint4*>(&As[buf][r][cs]) =
                make_uint4(f2tf32(ra[it].x), f2tf32(ra[it].y),
                           f2tf32(ra[it].z), f2tf32(ra[it].w));
        }
        #pragma unroll
        for (int it = 0; it < BITER; ++it) {
            int idx = tid + it * 256;
            int n4 = (idx & (BN / 4 - 1)) * 4;
            int k  = idx / (BN / 4);
            Bs[buf][n4 + 0][k ^ (((n4 + 0) & 7) << 2)] = f2tf32(rb[it].x);
            Bs[buf][n4 + 1][k ^ (((n4 + 1) & 7) << 2)] = f2tf32(rb[it].y);
            Bs[buf][n4 + 2][k ^ (((n4 + 2) & 7) << 2)] = f2tf32(rb[it].z);
            Bs[buf][n4 + 3][k ^ (((n4 + 3) & 7) << 2)] = f2tf32(rb[it].w);
        }
    };

    float acc[MT][NT][4];
    #pragma unroll
    for (int mi = 0; mi < MT; mi++)
        #pragma unroll
        for (int ni = 0; ni < NT; ni++)
            #pragma unroll
            for (int q = 0; q < 4; q++) acc[mi][ni][q] = 0.f;

    gload(0);
    sstore(0);
    __syncthreads();

    const int KT = K / 32;
    for (int kt = 0; kt < KT; ++kt) {
        if (kt + 1 < KT) gload((kt + 1) * 32);
        int buf = kt & 1;
        #pragma unroll
        for (int kk = 0; kk < 32; kk += 8) {
            uint32_t af[MT][4], bf[NT][2];
            int c0 = (kk + tg) ^ sw;
            int c1 = (kk + tg + 4) ^ sw;
            #pragma unroll
            for (int mi = 0; mi < MT; mi++) {
                int r0 = wm * WM + mi * 16 + g;
                af[mi][0] = As[buf][r0][c0];
                af[mi][1] = As[buf][r0 + 8][c0];
                af[mi][2] = As[buf][r0][c1];
                af[mi][3] = As[buf][r0 + 8][c1];
            }
            #pragma unroll
            for (int ni = 0; ni < NT; ni++) {
                int nn = wn * WN + ni * 8 + g;
                bf[ni][0] = Bs[buf][nn][c0];
                bf[ni][1] = Bs[buf][nn][c1];
            }
            #pragma unroll
            for (int mi = 0; mi < MT; mi++)
                #pragma unroll
                for (int ni = 0; ni < NT; ni++)
                    mma_tf32(acc[mi][ni], af[mi], bf[ni]);
        }
        if (kt + 1 < KT) {
            sstore((kt + 1) & 1);
            __syncthreads();
        }
    }

    // ---- epilogue: store h as half2 + fused alpha dots ----
    float ps[MT][2], pd[MT][2];
    #pragma unroll
    for (int mi = 0; mi < MT; mi++) {
        ps[mi][0] = ps[mi][1] = 0.f;
        pd[mi][0] = pd[mi][1] = 0.f;
    }
    #pragma unroll
    for (int mi = 0; mi < MT; mi++) {
        int r = rowBase + wm * WM + mi * 16 + g;
        #pragma unroll
        for (int ni = 0; ni < NT; ni++) {
            int cl = wn * WN + ni * 8 + tg * 2;       // col within head
            float as0 = av_s[head * 64 + cl], as1 = av_s[head * 64 + cl + 1];
            float ad0 = av_d[head * 64 + cl], ad1 = av_d[head * 64 + cl + 1];
            ps[mi][0] = fmaf(acc[mi][ni][0], as0, fmaf(acc[mi][ni][1], as1, ps[mi][0]));
            pd[mi][0] = fmaf(acc[mi][ni][0], ad0, fmaf(acc[mi][ni][1], ad1, pd[mi][0]));
            ps[mi][1] = fmaf(acc[mi][ni][2], as0, fmaf(acc[mi][ni][3], as1, ps[mi][1]));
            pd[mi][1] = fmaf(acc[mi][ni][2], ad0, fmaf(acc[mi][ni][3], ad1, pd[mi][1]));
            int c = colBase + cl;
            if (r < M)
                *reinterpret_cast<__half2*>(C + (size_t)r * N + c) =
                    __floats2half2_rn(acc[mi][ni][0], acc[mi][ni][1]);
            if (r + 8 < M)
                *reinterpret_cast<__half2*>(C + (size_t)(r + 8) * N + c) =
                    __floats2half2_rn(acc[mi][ni][2], acc[mi][ni][3]);
        }
    }
    // reduce over the 4 tg lanes (same row)
    #pragma unroll
    for (int off = 1; off < 4; off <<= 1) {
        #pragma unroll
        for (int mi = 0; mi < MT; mi++) {
            #pragma unroll
            for (int q = 0; q < 2; q++) {
                ps[mi][q] += __shfl_xor_sync(0xffffffffu, ps[mi][q], off);
                pd[mi][q] += __shfl_xor_sync(0xffffffffu, pd[mi][q], off);
            }
        }
    }
    // combine the two column-warps via smem
    if (wn == 1 && tg == 0) {
        #pragma unroll
        for (int mi = 0; mi < MT; mi++)
            #pragma unroll
            for (int q = 0; q < 2; q++) {
                int rl = wm * WM + mi * 16 + g + q * 8;
                sred[rl][0] = ps[mi][q];
                sred[rl][1] = pd[mi][q];
            }
    }
    __syncthreads();
    if (wn == 0 && tg == 0) {
        #pragma unroll
        for (int mi = 0; mi < MT; mi++)
            #pragma unroll
            for (int q = 0; q < 2; q++) {
                int rl = wm * WM + mi * 16 + g + q * 8;
                int r = rowBase + rl;
                if (r < M) {
                    g_as[r * H + head] = ps[mi][q] + sred[rl][0];
                    g_ad[r * H + head] = pd[mi][q] + sred[rl][1];
                }
            }
    }
}

// ------------- per-dst softmax (2 passes; normalization deferred) -----------

template <int H>
__global__ void k_att(int n) {
    int gw = (blockIdx.x * blockDim.x + threadIdx.x) >> 5;
    int lane = threadIdx.x & 31;
    if (gw >= n) return;
    int r0 = g_rowptr[gw], r1 = g_rowptr[gw + 1];
    float ad[H], mx[H];
    #pragma unroll
    for (int hh = 0; hh < H; ++hh) { ad[hh] = g_ad[gw * H + hh]; mx[hh] = -1e30f; }
    for (int p = r0 + lane; p < r1; p += 32) {
        int s = g_adj[p];
        #pragma unroll
        for (int hh = 0; hh < H; ++hh) {
            float e = g_as[s * H + hh] + ad[hh];
            e = (e > 0.f) ? e : 0.2f * e;        // leaky_relu 0.2
            g_w[(size_t)p * H + hh] = e;
            mx[hh] = fmaxf(mx[hh], e);
        }
    }
    #pragma unroll
    for (int hh = 0; hh < H; ++hh)
        #pragma unroll
        for (int off = 16; off > 0; off >>= 1)
            mx[hh] = fmaxf(mx[hh], __shfl_xor_sync(0xffffffffu, mx[hh], off));
    float sm[H];
    #pragma unroll
    for (int hh = 0; hh < H; ++hh) sm[hh] = 0.f;
    for (int p = r0 + lane; p < r1; p += 32) {
        #pragma unroll
        for (int hh = 0; hh < H; ++hh) {
            float ex = expf(g_w[(size_t)p * H + hh] - mx[hh]);
            g_w[(size_t)p * H + hh] = ex;       // unnormalized; g_inv fixes it
            sm[hh] += ex;
        }
    }
    #pragma unroll
    for (int hh = 0; hh < H; ++hh)
        #pragma unroll
        for (int off = 16; off > 0; off >>= 1)
            sm[hh] += __shfl_xor_sync(0xffffffffu, sm[hh], off);
    if (lane == 0) {
        #pragma unroll
        for (int hh = 0; hh < H; ++hh)
            g_inv[gw * H + hh] = 1.f / (sm[hh] + 1e-16f);
    }
}

// --------------------------- aggregation (warp/dst) -------------------------
// H=4: lane owns 8 contiguous cols (head = lane/8); one 16B fp16 gather/edge.

template <bool RELU>
__global__ void k_agg4(const __half* __restrict__ hin, const float* __restrict__ bias,
                       float* __restrict__ out, int n) {
    int dst = (blockIdx.x * blockDim.x + threadIdx.x) >> 5;
    int lane = threadIdx.x & 31;
    if (dst >= n) return;
    int head = lane >> 3;
    int cb = lane << 3;
    float acc[8];
    #pragma unroll
    for (int q = 0; q < 8; q++) acc[q] = 0.f;
    int p = g_rowptr[dst], pe = g_rowptr[dst + 1];
    for (; p + 1 < pe; p += 2) {
        int sA = g_adj[p], sB = g_adj[p + 1];
        float wA = g_w[(size_t)p * 4 + head];
        float wB = g_w[(size_t)(p + 1) * 4 + head];
        uint4 ua = *reinterpret_cast<const uint4*>(hin + (size_t)sA * 256 + cb);
        uint4 ub = *reinterpret_cast<const uint4*>(hin + (size_t)sB * 256 + cb);
        const __half2* ha = reinterpret_cast<const __half2*>(&ua);
        const __half2* hb = reinterpret_cast<const __half2*>(&ub);
        #pragma unroll
        for (int q = 0; q < 4; q++) {
            float2 fa = __half22float2(ha[q]);
            float2 fb = __half22float2(hb[q]);
            acc[2 * q]     = fmaf(wA, fa.x, acc[2 * q]);
            acc[2 * q + 1] = fmaf(wA, fa.y, acc[2 * q + 1]);
            acc[2 * q]     = fmaf(wB, fb.x, acc[2 * q]);
            acc[2 * q + 1] = fmaf(wB, fb.y, acc[2 * q + 1]);
        }
    }
    if (p < pe) {
        int s = g_adj[p];
        float w = g_w[(size_t)p * 4 + head];
        uint4 ua = *reinterpret_cast<const uint4*>(hin + (size_t)s * 256 + cb);
        const __half2* ha = reinterpret_cast<const __half2*>(&ua);
        #pragma unroll
        for (int q = 0; q < 4; q++) {
            float2 fa = __half22float2(ha[q]);
            acc[2 * q]     = fmaf(w, fa.x, acc[2 * q]);
            acc[2 * q + 1] = fmaf(w, fa.y, acc[2 * q + 1]);
        }
    }
    float inv = g_inv[dst * 4 + head];
    float4 bv0 = *reinterpret_cast<const float4*>(bias + cb);
    float4 bv1 = *reinterpret_cast<const float4*>(bias + cb + 4);
    float4 o0, o1;
    o0.x = fmaf(acc[0], inv, bv0.x); o0.y = fmaf(acc[1], inv, bv0.y);
    o0.z = fmaf(acc[2], inv, bv0.z); o0.w = fmaf(acc[3], inv, bv0.w);
    o1.x = fmaf(acc[4], inv, bv1.x); o1.y = fmaf(acc[5], inv, bv1.y);
    o1.z = fmaf(acc[6], inv, bv1.z); o1.w = fmaf(acc[7], inv, bv1.w);
    if (RELU) {
        o0.x = fmaxf(o0.x, 0.f); o0.y = fmaxf(o0.y, 0.f);
        o0.z = fmaxf(o0.z, 0.f); o0.w = fmaxf(o0.w, 0.f);
        o1.x = fmaxf(o1.x, 0.f); o1.y = fmaxf(o1.y, 0.f);
        o1.z = fmaxf(o1.z, 0.f); o1.w = fmaxf(o1.w, 0.f);
    }
    float* op = out + (size_t)dst * 256 + cb;
    *reinterpret_cast<float4*>(op) = o0;
    *reinterpret_cast<float4*>(op + 4) = o1;
}

// H=1 (HC=64): lane owns 2 cols, half2 gathers.
template <bool RELU>
__global__ void k_agg1(const __half* __restrict__ hin, const float* __restrict__ bias,
                       float* __restrict__ out, int n) {
    int dst = (blockIdx.x * blockDim.x + threadIdx.x) >> 5;
    int lane = threadIdx.x & 31;
    if (dst >= n) return;
    int cb = lane << 1;
    float a0 = 0.f, a1 = 0.f;
    int p = g_rowptr[dst], pe = g_rowptr[dst + 1];
    for (; p + 1 < pe; p += 2) {
        int sA = g_adj[p], sB = g_adj[p + 1];
        float wA = g_w[p], wB = g_w[p + 1];
        float2 hA = __half22float2(*reinterpret_cast<const __half2*>(hin + (size_t)sA * 64 + cb));
        float2 hB = __half22float2(*reinterpret_cast<const __half2*>(hin + (size_t)sB * 64 + cb));
        a0 = fmaf(wA, hA.x, a0); a1 = fmaf(wA, hA.y, a1);
        a0 = fmaf(wB, hB.x, a0); a1 = fmaf(wB, hB.y, a1);
    }
    if (p < pe) {
        int s = g_adj[p];
        float w = g_w[p];
        float2 hA = __half22float2(*reinterpret_cast<const __half2*>(hin + (size_t)s * 64 + cb));
        a0 = fmaf(w, hA.x, a0); a1 = fmaf(w, hA.y, a1);
    }
    float inv = g_inv[dst];
    float2 bv = *reinterpret_cast<const float2*>(bias + cb);
    float2 o;
    o.x = fmaf(a0, inv, bv.x);
    o.y = fmaf(a1, inv, bv.y);
    if (RELU) { o.x = fmaxf(o.x, 0.f); o.y = fmaxf(o.y, 0.f); }
    *reinterpret_cast<float2*>(out + (size_t)dst * 64 + cb) = o;
}

// ------------------------- mean pool + head ---------------------------------

__global__ void k_reduce(const float* __restrict__ h2, int n) {
    __shared__ float sh[256];
    int c = threadIdx.x & 63;
    int rl = threadIdx.x >> 6;
    int rbase = blockIdx.x * 256;
    int rend = min(n, rbase + 256);
    float acc = 0.f;
    for (int r = rbase + rl; r < rend; r += 4)
        acc += h2[(size_t)r * 64 + c];
    sh[threadIdx.x] = acc;
    __syncthreads();
    if (threadIdx.x < 64) {
        float v = sh[threadIdx.x] + sh[threadIdx.x + 64] +
                  sh[threadIdx.x + 128] + sh[threadIdx.x + 192];
        atomicAdd(&g_gsum[threadIdx.x], v);
    }
}

__global__ void k_head(const float* __restrict__ hw, const float* __restrict__ hb,
                       float* __restrict__ out, float invN) {
    int o = threadIdx.x;   // 64 threads
    float acc = hb[o];
    #pragma unroll 8
    for (int c = 0; c < 64; ++c)
        acc = fmaf(g_gsum[c] * invN, hw[c * 64 + o], acc);
    out[o] = acc;
}

// ------------------------------ launch --------------------------------------

extern "C" void kernel_launch(void* const* d_in, const int* in_sizes, int n_in,
                              void* d_out, int out_size) {
    const float* x   = (const float*)d_in[0];
    const void*  ei  = d_in[1];
    const float* W0  = (const float*)d_in[2];
    const float* a0s = (const float*)d_in[3];
    const float* a0d = (const float*)d_in[4];
    const float* b0  = (const float*)d_in[5];
    const float* W1  = (const float*)d_in[6];
    const float* a1s = (const float*)d_in[7];
    const float* a1d = (const float*)d_in[8];
    const float* b1  = (const float*)d_in[9];
    const float* W2  = (const float*)d_in[10];
    const float* a2s = (const float*)d_in[11];
    const float* a2d = (const float*)d_in[12];
    const float* b2  = (const float*)d_in[13];
    const float* hw  = (const float*)d_in[14];
    const float* hb  = (const float*)d_in[15];
    float* out = (float*)d_out;

    int n = in_sizes[0] / 128;   // 50000
    int e = in_sizes[1] / 2;     // 800000

    __half *hA, *h2h;
    float *bufB, *out2p;
    cudaGetSymbolAddress((void**)&hA,    g_hA);
    cudaGetSymbolAddress((void**)&h2h,   g_h2h);
    cudaGetSymbolAddress((void**)&bufB,  g_bufB);
    cudaGetSymbolAddress((void**)&out2p, g_out2);

    int wblocks = (n + 7) / 8;                 // warp-per-node kernels
    int nb = (n + 1023) / 1024;

    // CSR build (by dst, with implicit self loops)
    k_init   <<<(n + 255) / 256, 256>>>(n);
    k_detect <<<1, 256>>>((const int*)ei);
    k_prep   <<<(e + 255) / 256, 256>>>(ei, e, n);
    k_scan1  <<<nb, 1024>>>(n);
    k_scan2  <<<1, 64>>>(nb, n);
    k_scan3  <<<nb, 1024>>>(n);
    k_scatter<<<(e + n + 255) / 256, 256>>>(e, n);

    dim3 g01((n + 127) / 128, 4);              // N=256, BN=64
    dim3 g2 ((n + 127) / 128, 1);              // N=64

    // ---- layer 0 ----
    k_gemm_f<4><<<g01, 256>>>(x, W0, hA, a0s, a0d, n, 256, 128);
    k_att<4><<<wblocks, 256>>>(n);
    k_agg4<true><<<(n + 7) / 8, 256>>>(hA, b0, bufB, n);

    // ---- layer 1 ----
    k_gemm_f<4><<<g01, 256>>>(bufB, W1, hA, a1s, a1d, n, 256, 256);
    k_att<4><<<wblocks, 256>>>(n);
    k_agg4<true><<<(n + 7) / 8, 256>>>(hA, b1, bufB, n);

    // ---- layer 2 ----
    k_gemm_f<1><<<g2, 256>>>(bufB, W2, h2h, a2s, a2d, n, 64, 256);
    k_att<1><<<wblocks, 256>>>(n);
    k_agg1<false><<<(n + 7) / 8, 256>>>(h2h, b2, out2p, n);

    // ---- mean over nodes + linear head ----
    k_reduce<<<(n + 255) / 256, 256>>>(out2p, n);
    k_head<<<1, 64>>>(hw, hb, out, 1.0f / (float)n);
}

// round 17
// speedup vs baseline: 1.4540x; 1.1635x over previous
#include <cuda_runtime.h>
#include <cuda_fp16.h>
#include <math.h>
#include <stdint.h>

// ---------------------------------------------------------------------------
// GAT_23888608101379: 3-layer GAT + mean pool + linear head.
//  R16: - fp16 HMMA GEMM (m16n8k16, fp32 accum), BK=64, double-buffered
//       - softmax fused into aggregation (online max/sum in registers;
//         k_att and g_w eliminated)
//       - aggregation outputs fp16 (feeds fp16 GEMM A directly)
// ---------------------------------------------------------------------------

constexpr int CN = 50000;            // nodes
constexpr int CE = 800000;           // edges
constexpr int CT = CE + CN;          // edges + self loops

__device__ __half g_hA  [(size_t)CN * 256];  // GEMM output h (layers 0/1)
__device__ __half g_aggH[(size_t)CN * 256];  // agg output (GEMM A input)
__device__ __half g_h2h [(size_t)CN * 64];   // GEMM output h (layer 2)
__device__ float  g_out2[(size_t)CN * 64];
__device__ float  g_as  [CN * 4];
__device__ float  g_ad  [CN * 4];
__device__ int    g_src [CE];
__device__ int    g_dst [CE];
__device__ int    g_rowptr[CN + 1];
__device__ int    g_counts[CN];
__device__ int    g_cursor[CN];
__device__ int    g_adj   [CT];
__device__ int    g_bsum[64];
__device__ float  g_gsum[64];
__device__ int    g_is64;

// ----------------------- edge dtype detect ---------------------------------

__global__ void k_detect(const int* __restrict__ w) {
    __shared__ int any;
    if (threadIdx.x == 0) any = 0;
    __syncthreads();
    for (int i = threadIdx.x; i < 4096; i += blockDim.x)
        if (w[2 * i + 1] != 0) any = 1;
    __syncthreads();
    if (threadIdx.x == 0) g_is64 = (any == 0) ? 1 : 0;
}

__global__ void k_init(int n) {
    int i = blockIdx.x * blockDim.x + threadIdx.x;
    if (i < n)  g_counts[i] = 1;      // self loop
    if (i < 64) g_gsum[i] = 0.f;
}

// convert (int32/int64) + histogram in one pass
__global__ void k_prep(const void* __restrict__ ei, int e, int n) {
    int i = blockIdx.x * blockDim.x + threadIdx.x;
    if (i >= e) return;
    int s, d;
    if (g_is64) {
        const long long* p = (const long long*)ei;
        s = (int)p[i];
        d = (int)p[(size_t)e + i];
    } else {
        const int* p = (const int*)ei;
        s = p[i];
        d = p[(size_t)e + i];
    }
    g_src[i] = s;
    g_dst[i] = d;
    if (d >= 0 && d < n) atomicAdd(&g_counts[d], 1);
}

// ------------------------- multi-block scan ---------------------------------

__global__ void k_scan1(int n) {
    int b = blockIdx.x;
    int i = b * 1024 + threadIdx.x;
    int v = (i < n) ? g_counts[i] : 0;
    int lane = threadIdx.x & 31, wid = threadIdx.x >> 5;
    int s = v;
    #pragma unroll
    for (int off = 1; off < 32; off <<= 1) {
        int t = __shfl_up_sync(0xffffffffu, s, off);
        if (lane >= off) s += t;
    }
    __shared__ int wsum[32];
    if (lane == 31) wsum[wid] = s;
    __syncthreads();
    if (wid == 0) {
        int ws = wsum[lane];
        #pragma unroll
        for (int off = 1; off < 32; off <<= 1) {
            int t = __shfl_up_sync(0xffffffffu, ws, off);
            if (lane >= off) ws += t;
        }
        wsum[lane] = ws;
    }
    __syncthreads();
    int base = (wid > 0) ? wsum[wid - 1] : 0;
    int excl = base + s - v;
    if (i < n) g_rowptr[i] = excl;
    if (threadIdx.x == 1023) g_bsum[b] = excl + v;
}

__global__ void k_scan2(int nb, int n) {
    int t = threadIdx.x;                     // 64 threads, nb <= 64
    int v = (t < nb) ? g_bsum[t] : 0;
    int lane = t & 31, w = t >> 5;
    int s = v;
    #pragma unroll
    for (int off = 1; off < 32; off <<= 1) {
        int tt = __shfl_up_sync(0xffffffffu, s, off);
        if (lane >= off) s += tt;
    }
    __shared__ int ws0;
    if (w == 0 && lane == 31) ws0 = s;
    __syncthreads();
    int incl = s + ((w == 1) ? ws0 : 0);
    int excl = incl - v;
    if (t < nb) g_bsum[t] = excl;
    if (t == nb - 1) g_rowptr[n] = incl;
}

__global__ void k_scan3(int n) {
    int i = blockIdx.x * blockDim.x + threadIdx.x;
    if (i < n) {
        int rp = g_rowptr[i] + g_bsum[i >> 10];
        g_rowptr[i] = rp;
        g_cursor[i] = rp;
    }
}

__global__ void k_scatter(int e, int n) {
    int i = blockIdx.x * blockDim.x + threadIdx.x;
    if (i < e) {
        int s = g_src[i];
        int d = g_dst[i];
        if (d >= 0 && d < n && s >= 0 && s < n) {
            int pos = atomicAdd(&g_cursor[d], 1);
            g_adj[pos] = s;
        }
    } else if (i < e + n) {
        int nd = i - e;                       // self loop
        int pos = atomicAdd(&g_cursor[nd], 1);
        g_adj[pos] = nd;
    }
}

// ------------- fp16 HMMA GEMM + fused alpha epilogue, fp16 C ----------------
// C[M,N] = A[M,K] @ B[K,N]; BM=128, BN=64, BK=64 halves; 256 threads
// (8 warps, WM=WN=32, 4x2 warp grid). BN==64 == head width -> alpha dots
// per (row, head=blockIdx.y) computed from fp32 accumulators in-block.
// A: fp32 (layer0, converted at load) or fp16 (layers 1/2, from agg).
// B: fp32 weights converted RN at smem fill.

__device__ __forceinline__ uint32_t packh2(float a, float b) {
    __half2 h = __floats2half2_rn(a, b);
    return *reinterpret_cast<uint32_t*>(&h);
}

__device__ __forceinline__ void mma_f16(float* c,
                                        const uint32_t* a, const uint32_t* b) {
    asm volatile(
        "mma.sync.aligned.m16n8k16.row.col.f32.f16.f16.f32 "
        "{%0,%1,%2,%3}, {%4,%5,%6,%7}, {%8,%9}, {%0,%1,%2,%3};\n"
        : "+f"(c[0]), "+f"(c[1]), "+f"(c[2]), "+f"(c[3])
        : "r"(a[0]), "r"(a[1]), "r"(a[2]), "r"(a[3]), "r"(b[0]), "r"(b[1]));
}

template <int H, typename TA>
__global__ __launch_bounds__(256, 2) void k_gemm_h(const TA* __restrict__ A,
                                                   const float* __restrict__ B,
                                                   __half* __restrict__ C,
                                                   const float* __restrict__ av_s,
                                                   const float* __restrict__ av_d,
                                                   int M, int N, int K) {
    constexpr int WM = 32, WN = 32;
    constexpr int WARPS_M = 4;
    constexpr int MT = 2, NT = 4;
    constexpr bool A16 = (sizeof(TA) == 2);

    // half2 words: As[r][w] covers halves (2w, 2w+1) of row r; 32-word rows.
    __shared__ uint32_t As[2][128][32];
    __shared__ uint32_t Bs[2][64][32];
    __shared__ float sred[128][2];

    const int tid  = threadIdx.x;
    const int wid  = tid >> 5;
    const int lane = tid & 31;
    const int g    = lane >> 2;
    const int tg   = lane & 3;
    const int sw   = g << 2;

    const int wm = wid % WARPS_M;
    const int wn = wid / WARPS_M;
    const int rowBase = blockIdx.x * 128;
    const int colBase = blockIdx.y * 64;
    const int head = blockIdx.y;

    uint4 ra[4];          // 32 halves of A (converted), per thread
    uint32_t rbh[2][4];   // 8 packed half2 of B, per thread

    auto gload = [&](int k0) {
        if constexpr (A16) {
            #pragma unroll
            for (int it = 0; it < 4; ++it) {
                int idx = tid + it * 256;
                int r = idx >> 3, part = idx & 7;      // 8 uint4 per 64-half row
                int gr = rowBase + r;
                ra[it] = (gr < M)
                    ? *reinterpret_cast<const uint4*>(
                          (const __half*)A + (size_t)gr * K + k0 + part * 8)
                    : make_uint4(0u, 0u, 0u, 0u);
            }
        } else {
            #pragma unroll
            for (int it = 0; it < 4; ++it) {
                int idx = tid + it * 256;
                int r = idx >> 3, part = idx & 7;
                int gr = rowBase + r;
                float4 v0 = make_float4(0.f, 0.f, 0.f, 0.f), v1 = v0;
                if (gr < M) {
                    const float* ap = (const float*)A + (size_t)gr * K + k0 + part * 8;
                    v0 = *reinterpret_cast<const float4*>(ap);
                    v1 = *reinterpret_cast<const float4*>(ap + 4);
                }
                ra[it] = make_uint4(packh2(v0.x, v0.y), packh2(v0.z, v0.w),
                                    packh2(v1.x, v1.y), packh2(v1.z, v1.w));
            }
        }
        #pragma unroll
        for (int it = 0; it < 2; ++it) {
            int idx = tid + it * 256;
            int kp = idx >> 4;                 // 32 k-pairs
            int n4 = (idx & 15) * 4;
            const float* bp = B + (size_t)(k0 + 2 * kp) * N + colBase + n4;
            float4 va = *reinterpret_cast<const float4*>(bp);
            float4 vb = *reinterpret_cast<const float4*>(bp + N);
            rbh[it][0] = packh2(va.x, vb.x);
            rbh[it][1] = packh2(va.y, vb.y);
            rbh[it][2] = packh2(va.z, vb.z);
            rbh[it][3] = packh2(va.w, vb.w);
        }
    };
    auto sstore = [&](int buf) {
        #pragma unroll
        for (int it = 0; it < 4; ++it) {
            int idx = tid + it * 256;
            int r = idx >> 3, part = idx & 7;
            int w0 = (part * 4) ^ ((r & 7) << 2);
            *reinterpret_cast<uint4*>(&As[buf][r][w0]) = ra[it];
        }
        #pragma unroll
        for (int it = 0; it < 2; ++it) {
            int idx = tid + it * 256;
            int kp = idx >> 4;
            int n4 = (idx & 15) * 4;
            #pragma unroll
            for (int i = 0; i < 4; ++i)
                Bs[buf][n4 + i][kp ^ (((n4 + i) & 7) << 2)] = rbh[it][i];
        }
    };

    float acc[MT][NT][4];
    #pragma unroll
    for (int mi = 0; mi < MT; mi++)
        #pragma unroll
        for (int ni = 0; ni < NT; ni++)
            #pragma unroll
            for (int q = 0; q < 4; q++) acc[mi][ni][q] = 0.f;

    gload(0);
    sstore(0);
    __syncthreads();

    const int KT = K / 64;
    for (int kt = 0; kt < KT; ++kt) {
        if (kt + 1 < KT) gload((kt + 1) * 64);
        int buf = kt & 1;
        #pragma unroll
        for (int kk = 0; kk < 4; ++kk) {       // 4 k16 steps per 64-half tile
            uint32_t af[MT][4], bf[NT][2];
            int c0 = (kk * 8 + tg) ^ sw;
            int c1 = (kk * 8 + tg + 4) ^ sw;
            #pragma unroll
            for (int mi = 0; mi < MT; mi++) {
                int r0 = wm * WM + mi * 16 + g;
                af[mi][0] = As[buf][r0][c0];
                af[mi][1] = As[buf][r0 + 8][c0];
                af[mi][2] = As[buf][r0][c1];
                af[mi][3] = As[buf][r0 + 8][c1];
            }
            #pragma unroll
            for (int ni = 0; ni < NT; ni++) {
                int nn = wn * WN + ni * 8 + g;
                bf[ni][0] = Bs[buf][nn][c0];
                bf[ni][1] = Bs[buf][nn][c1];
            }
            #pragma unroll
            for (int mi = 0; mi < MT; mi++)
                #pragma unroll
                for (int ni = 0; ni < NT; ni++)
                    mma_f16(acc[mi][ni], af[mi], bf[ni]);
        }
        if (kt + 1 < KT) {
            sstore((kt + 1) & 1);
            __syncthreads();
        }
    }

    // ---- epilogue: store h as half2 + fused alpha dots ----
    float ps[MT][2], pd[MT][2];
    #pragma unroll
    for (int mi = 0; mi < MT; mi++) {
        ps[mi][0] = ps[mi][1] = 0.f;
        pd[mi][0] = pd[mi][1] = 0.f;
    }
    #pragma unroll
    for (int mi = 0; mi < MT; mi++) {
        int r = rowBase + wm * WM + mi * 16 + g;
        #pragma unroll
        for (int ni = 0; ni < NT; ni++) {
            int cl = wn * WN + ni * 8 + tg * 2;       // col within head
            float as0 = av_s[head * 64 + cl], as1 = av_s[head * 64 + cl + 1];
            float ad0 = av_d[head * 64 + cl], ad1 = av_d[head * 64 + cl + 1];
            ps[mi][0] = fmaf(acc[mi][ni][0], as0, fmaf(acc[mi][ni][1], as1, ps[mi][0]));
            pd[mi][0] = fmaf(acc[mi][ni][0], ad0, fmaf(acc[mi][ni][1], ad1, pd[mi][0]));
            ps[mi][1] = fmaf(acc[mi][ni][2], as0, fmaf(acc[mi][ni][3], as1, ps[mi][1]));
            pd[mi][1] = fmaf(acc[mi][ni][2], ad0, fmaf(acc[mi][ni][3], ad1, pd[mi][1]));
            int c = colBase + cl;
            if (r < M)
                *reinterpret_cast<__half2*>(C + (size_t)r * N + c) =
                    __floats2half2_rn(acc[mi][ni][0], acc[mi][ni][1]);
            if (r + 8 < M)
                *reinterpret_cast<__half2*>(C + (size_t)(r + 8) * N + c) =
                    __floats2half2_rn(acc[mi][ni][2], acc[mi][ni][3]);
        }
    }
    #pragma unroll
    for (int off = 1; off < 4; off <<= 1) {
        #pragma unroll
        for (int mi = 0; mi < MT; mi++) {
            #pragma unroll
            for (int q = 0; q < 2; q++) {
                ps[mi][q] += __shfl_xor_sync(0xffffffffu, ps[mi][q], off);
                pd[mi][q] += __shfl_xor_sync(0xffffffffu, pd[mi][q], off);
            }
        }
    }
    if (wn == 1 && tg == 0) {
        #pragma unroll
        for (int mi = 0; mi < MT; mi++)
            #pragma unroll
            for (int q = 0; q < 2; q++) {
                int rl = wm * WM + mi * 16 + g + q * 8;
                sred[rl][0] = ps[mi][q];
                sred[rl][1] = pd[mi][q];
            }
    }
    __syncthreads();
    if (wn == 0 && tg == 0) {
        #pragma unroll
        for (int mi = 0; mi < MT; mi++)
            #pragma unroll
            for (int q = 0; q < 2; q++) {
                int rl = wm * WM + mi * 16 + g + q * 8;
                int r = rowBase + rl;
                if (r < M) {
                    g_as[r * H + head] = ps[mi][q] + sred[rl][0];
                    g_ad[r * H + head] = pd[mi][q] + sred[rl][1];
                }
            }
    }
}

// ----------------- fused softmax + aggregation (warp/dst) -------------------
// Pass 1: online max/sum of exp(lrelu(as[src]+ad[dst])) per head (lanes
// stride edges), warp-combine -> m, inv in registers.
// Pass 2: recompute w inline, gather fp16 h rows, accumulate, emit fp16.

template <bool RELU>
__global__ void k_agg4(const __half* __restrict__ hin, const float* __restrict__ bias,
                       __half* __restrict__ out, int n) {
    int dst = (blockIdx.x * blockDim.x + threadIdx.x) >> 5;
    int lane = threadIdx.x & 31;
    if (dst >= n) return;
    int head = lane >> 3;
    int cb = lane << 3;
    int r0 = g_rowptr[dst], r1 = g_rowptr[dst + 1];

    float4 adv = *reinterpret_cast<const float4*>(&g_ad[dst * 4]);
    float ad[4] = {adv.x, adv.y, adv.z, adv.w};
    float m[4] = {-1e30f, -1e30f, -1e30f, -1e30f};
    float sm[4] = {0.f, 0.f, 0.f, 0.f};

    for (int p = r0 + lane; p < r1; p += 32) {
        int s = g_adj[p];
        float4 asv = *reinterpret_cast<const float4*>(&g_as[s * 4]);
        float ev[4] = {asv.x + ad[0], asv.y + ad[1], asv.z + ad[2], asv.w + ad[3]};
        #pragma unroll
        for (int h = 0; h < 4; ++h) {
            float e = ev[h] > 0.f ? ev[h] : 0.2f * ev[h];
            if (e > m[h]) {
                sm[h] = fmaf(sm[h], __expf(m[h] - e), 1.f);
                m[h] = e;
            } else {
                sm[h] += __expf(e - m[h]);
            }
        }
    }
    #pragma unroll
    for (int off = 16; off > 0; off >>= 1) {
        #pragma unroll
        for (int h = 0; h < 4; ++h) {
            float mo = __shfl_xor_sync(0xffffffffu, m[h], off);
            float so = __shfl_xor_sync(0xffffffffu, sm[h], off);
            float mn = fmaxf(m[h], mo);
            sm[h] = sm[h] * __expf(m[h] - mn) + so * __expf(mo - mn);
            m[h] = mn;
        }
    }
    float Mh  = (head == 0) ? m[0] : (head == 1) ? m[1] : (head == 2) ? m[2] : m[3];
    float Sh  = (head == 0) ? sm[0] : (head == 1) ? sm[1] : (head == 2) ? sm[2] : sm[3];
    float adh = ad[0];
    adh = (head == 1) ? ad[1] : adh; adh = (head == 2) ? ad[2] : adh;
    adh = (head == 3) ? ad[3] : adh;
    float inv = 1.f / (Sh + 1e-16f);

    float acc[8];
    #pragma unroll
    for (int q = 0; q < 8; q++) acc[q] = 0.f;

    int p = r0;
    for (; p + 1 < r1; p += 2) {
        int sA = g_adj[p], sB = g_adj[p + 1];
        float eA = g_as[sA * 4 + head] + adh;
        float eB = g_as[sB * 4 + head] + adh;
        eA = eA > 0.f ? eA : 0.2f * eA;
        eB = eB > 0.f ? eB : 0.2f * eB;
        float wA = __expf(eA - Mh);
        float wB = __expf(eB - Mh);
        uint4 ua = *reinterpret_cast<const uint4*>(hin + (size_t)sA * 256 + cb);
        uint4 ub = *reinterpret_cast<const uint4*>(hin + (size_t)sB * 256 + cb);
        const __half2* ha = reinterpret_cast<const __half2*>(&ua);
        const __half2* hb = reinterpret_cast<const __half2*>(&ub);
        #pragma unroll
        for (int q = 0; q < 4; q++) {
            float2 fa = __half22float2(ha[q]);
            float2 fb = __half22float2(hb[q]);
            acc[2 * q]     = fmaf(wA, fa.x, acc[2 * q]);
            acc[2 * q + 1] = fmaf(wA, fa.y, acc[2 * q + 1]);
            acc[2 * q]     = fmaf(wB, fb.x, acc[2 * q]);
            acc[2 * q + 1] = fmaf(wB, fb.y, acc[2 * q + 1]);
        }
    }
    if (p < r1) {
        int s = g_adj[p];
        float e = g_as[s * 4 + head] + adh;
        e = e > 0.f ? e : 0.2f * e;
        float w = __expf(e - Mh);
        uint4 ua = *reinterpret_cast<const uint4*>(hin + (size_t)s * 256 + cb);
        const __half2* ha = reinterpret_cast<const __half2*>(&ua);
        #pragma unroll
        for (int q = 0; q < 4; q++) {
            float2 fa = __half22float2(ha[q]);
            acc[2 * q]     = fmaf(w, fa.x, acc[2 * q]);
            acc[2 * q + 1] = fmaf(w, fa.y, acc[2 * q + 1]);
        }
    }
    float4 bv0 = *reinterpret_cast<const float4*>(bias + cb);
    float4 bv1 = *reinterpret_cast<const float4*>(bias + cb + 4);
    float o[8];
    o[0] = fmaf(acc[0], inv, bv0.x); o[1] = fmaf(acc[1], inv, bv0.y);
    o[2] = fmaf(acc[2], inv, bv0.z); o[3] = fmaf(acc[3], inv, bv0.w);
    o[4] = fmaf(acc[4], inv, bv1.x); o[5] = fmaf(acc[5], inv, bv1.y);
    o[6] = fmaf(acc[6], inv, bv1.z); o[7] = fmaf(acc[7], inv, bv1.w);
    if (RELU) {
        #pragma unroll
        for (int q = 0; q < 8; q++) o[q] = fmaxf(o[q], 0.f);
    }
    uint4 pk;
    pk.x = packh2(o[0], o[1]); pk.y = packh2(o[2], o[3]);
    pk.z = packh2(o[4], o[5]); pk.w = packh2(o[6], o[7]);
    *reinterpret_cast<uint4*>(out + (size_t)dst * 256 + cb) = pk;
}

// H=1 (HC=64): lane owns 2 cols; fp32 output (feeds mean-reduce).
__global__ void k_agg1(const __half* __restrict__ hin, const float* __restrict__ bias,
                       float* __restrict__ out, int n) {
    int dst = (blockIdx.x * blockDim.x + threadIdx.x) >> 5;
    int lane = threadIdx.x & 31;
    if (dst >= n) return;
    int cb = lane << 1;
    int r0 = g_rowptr[dst], r1 = g_rowptr[dst + 1];

    float ad = g_ad[dst];
    float m = -1e30f, sm = 0.f;
    for (int p = r0 + lane; p < r1; p += 32) {
        int s = g_adj[p];
        float e = g_as[s] + ad;
        e = e > 0.f ? e : 0.2f * e;
        if (e > m) { sm = fmaf(sm, __expf(m - e), 1.f); m = e; }
        else       { sm += __expf(e - m); }
    }
    #pragma unroll
    for (int off = 16; off > 0; off >>= 1) {
        float mo = __shfl_xor_sync(0xffffffffu, m, off);
        float so = __shfl_xor_sync(0xffffffffu, sm, off);
        float mn = fmaxf(m, mo);
        sm = sm * __expf(m - mn) + so * __expf(mo - mn);
        m = mn;
    }
    float inv = 1.f / (sm + 1e-16f);

    float a0 = 0.f, a1 = 0.f;
    int p = r0;
    for (; p + 1 < r1; p += 2) {
        int sA = g_adj[p], sB = g_adj[p + 1];
        float eA = g_as[sA] + ad, eB = g_as[sB] + ad;
        eA = eA > 0.f ? eA : 0.2f * eA;
        eB = eB > 0.f ? eB : 0.2f * eB;
        float wA = __expf(eA - m), wB = __expf(eB - m);
        float2 hA = __half22float2(*reinterpret_cast<const __half2*>(hin + (size_t)sA * 64 + cb));
        float2 hB = __half22float2(*reinterpret_cast<const __half2*>(hin + (size_t)sB * 64 + cb));
        a0 = fmaf(wA, hA.x, a0); a1 = fmaf(wA, hA.y, a1);
        a0 = fmaf(wB, hB.x, a0); a1 = fmaf(wB, hB.y, a1);
    }
    if (p < r1) {
        int s = g_adj[p];
        float e = g_as[s] + ad;
        e = e > 0.f ? e : 0.2f * e;
        float w = __expf(e - m);
        float2 hA = __half22float2(*reinterpret_cast<const __half2*>(hin + (size_t)s * 64 + cb));
        a0 = fmaf(w, hA.x, a0); a1 = fmaf(w, hA.y, a1);
    }
    float2 bv = *reinterpret_cast<const float2*>(bias + cb);
    float2 o;
    o.x = fmaf(a0, inv, bv.x);
    o.y = fmaf(a1, inv, bv.y);
    *reinterpret_cast<float2*>(out + (size_t)dst * 64 + cb) = o;
}

// ------------------------- mean pool + head ---------------------------------

__global__ void k_reduce(const float* __restrict__ h2, int n) {
    __shared__ float sh[256];
    int c = threadIdx.x & 63;
    int rl = threadIdx.x >> 6;
    int rbase = blockIdx.x * 256;
    int rend = min(n, rbase + 256);
    float acc = 0.f;
    for (int r = rbase + rl; r < rend; r += 4)
        acc += h2[(size_t)r * 64 + c];
    sh[threadIdx.x] = acc;
    __syncthreads();
    if (threadIdx.x < 64) {
        float v = sh[threadIdx.x] + sh[threadIdx.x + 64] +
                  sh[threadIdx.x + 128] + sh[threadIdx.x + 192];
        atomicAdd(&g_gsum[threadIdx.x], v);
    }
}

__global__ void k_head(const float* __restrict__ hw, const float* __restrict__ hb,
                       float* __restrict__ out, float invN) {
    int o = threadIdx.x;   // 64 threads
    float acc = hb[o];
    #pragma unroll 8
    for (int c = 0; c < 64; ++c)
        acc = fmaf(g_gsum[c] * invN, hw[c * 64 + o], acc);
    out[o] = acc;
}

// ------------------------------ launch --------------------------------------

extern "C" void kernel_launch(void* const* d_in, const int* in_sizes, int n_in,
                              void* d_out, int out_size) {
    const float* x   = (const float*)d_in[0];
    const void*  ei  = d_in[1];
    const float* W0  = (const float*)d_in[2];
    const float* a0s = (const float*)d_in[3];
    const float* a0d = (const float*)d_in[4];
    const float* b0  = (const float*)d_in[5];
    const float* W1  = (const float*)d_in[6];
    const float* a1s = (const float*)d_in[7];
    const float* a1d = (const float*)d_in[8];
    const float* b1  = (const float*)d_in[9];
    const float* W2  = (const float*)d_in[10];
    const float* a2s = (const float*)d_in[11];
    const float* a2d = (const float*)d_in[12];
    const float* b2  = (const float*)d_in[13];
    const float* hw  = (const float*)d_in[14];
    const float* hb  = (const float*)d_in[15];
    float* out = (float*)d_out;

    int n = in_sizes[0] / 128;   // 50000
    int e = in_sizes[1] / 2;     // 800000

    __half *hA, *aggH, *h2h;
    float *out2p;
    cudaGetSymbolAddress((void**)&hA,    g_hA);
    cudaGetSymbolAddress((void**)&aggH,  g_aggH);
    cudaGetSymbolAddress((void**)&h2h,   g_h2h);
    cudaGetSymbolAddress((void**)&out2p, g_out2);

    int nb = (n + 1023) / 1024;
    int aggBlocks = (n + 7) / 8;               // 8 warps/block, warp per dst

    // CSR build (by dst, with implicit self loops)
    k_init   <<<(n + 255) / 256, 256>>>(n);
    k_detect <<<1, 256>>>((const int*)ei);
    k_prep   <<<(e + 255) / 256, 256>>>(ei, e, n);
    k_scan1  <<<nb, 1024>>>(n);
    k_scan2  <<<1, 64>>>(nb, n);
    k_scan3  <<<nb, 1024>>>(n);
    k_scatter<<<(e + n + 255) / 256, 256>>>(e, n);

    dim3 g01((n + 127) / 128, 4);              // N=256, BN=64
    dim3 g2 ((n + 127) / 128, 1);              // N=64

    // ---- layer 0: x fp32 -> h fp16; fused softmax+agg -> fp16 ----
    k_gemm_h<4, float><<<g01, 256>>>(x, W0, hA, a0s, a0d, n, 256, 128);
    k_agg4<true><<<aggBlocks, 256>>>(hA, b0, aggH, n);

    // ---- layer 1 ----
    k_gemm_h<4, __half><<<g01, 256>>>(aggH, W1, hA, a1s, a1d, n, 256, 256);
    k_agg4<true><<<aggBlocks, 256>>>(hA, b1, aggH, n);

    // ---- layer 2 ----
    k_gemm_h<1, __half><<<g2, 256>>>(aggH, W2, h2h, a2s, a2d, n, 64, 256);
    k_agg1<<<aggBlocks, 256>>>(h2h, b2, out2p, n);

    // ---- mean over nodes + linear head ----
    k_reduce<<<(n + 255) / 256, 256>>>(out2p, n);
    k_head<<<1, 64>>>(hw, hb, out, 1.0f / (float)n);
}